// round 15
// baseline (speedup 1.0000x reference)
#include <cuda_runtime.h>

#define DM   2048   // d_model
#define DS   16     // d_state
#define NB   8      // batch
#define LQ   512    // seq
#define NC   8      // chunks
#define LC   64     // chunk length (NC*LC == LQ)
#define HS   8      // states per thread in k_C (half of DS)

#define BDIM 128
#define SLAB (NB * DM * HS)   // floats per (half,chunk) slab = 131072

typedef unsigned long long ull;

// ---- chunk end-state scratch, split layout [half][c][b][d][HS] ----
__device__ float g_end[2 * (NC - 1) * SLAB];

// ---- packed f32x2 helpers ----
__device__ __forceinline__ ull pk(float lo, float hi) {
    ull r;
    asm("mov.b64 %0, {%1, %2};" : "=l"(r) : "f"(lo), "f"(hi));
    return r;
}
__device__ __forceinline__ void upk(ull v, float& lo, float& hi) {
    asm("mov.b64 {%0, %1}, %2;" : "=f"(lo), "=f"(hi) : "l"(v));
}
__device__ __forceinline__ ull fma2(ull a, ull b, ull c) {
    ull r;
    asm("fma.rn.f32x2 %0, %1, %2, %3;" : "=l"(r) : "l"(a), "l"(b), "l"(c));
    return r;
}
__device__ __forceinline__ ull mul2(ull a, ull b) {
    ull r;
    asm("mul.rn.f32x2 %0, %1, %2;" : "=l"(r) : "l"(a), "l"(b));
    return r;
}
__device__ __forceinline__ ull add2(ull a, ull b) {
    ull r;
    asm("add.rn.f32x2 %0, %1, %2;" : "=l"(r) : "l"(a), "l"(b));
    return r;
}

// ---- phase A: end states of chunks 0..NC-2, FULL state per thread ----
__global__ void __launch_bounds__(BDIM)
k_A(const float* __restrict__ x,
    const float* __restrict__ A_log,
    const float* __restrict__ log_dt) {
    int idx = blockIdx.x * BDIM + threadIdx.x;   // (NC-1)*NB*DM = 114688
    int d = idx & (DM - 1);
    int b = (idx >> 11) & (NB - 1);
    int c = idx >> 14;                           // 0..NC-2

    float dt = __expf(log_dt[d]);                // DT_SCALE = 1
    ull dA2[8];
    {
        const float4* pa = (const float4*)(A_log + (d << 4));
#pragma unroll
        for (int k = 0; k < 4; k++) {
            float4 v = pa[k];
            float a0 = __expf(dt * __expf(v.x));
            float a1 = __expf(dt * __expf(v.y));
            float a2 = __expf(dt * __expf(v.z));
            float a3 = __expf(dt * __expf(v.w));
            dA2[2 * k]     = pk(a0, a1);
            dA2[2 * k + 1] = pk(a2, a3);
        }
    }

    ull p2[8];
#pragma unroll
    for (int k = 0; k < 8; k++) p2[k] = 0ull;

    const float* xp = x + (size_t)(b * LQ + c * LC) * DM + d;
#pragma unroll 8
    for (int t = 0; t < LC; t++) {
        float xt = xp[(size_t)t * DM];
        ull xx = pk(xt, xt);
#pragma unroll
        for (int k = 0; k < 8; k++) p2[k] = fma2(dA2[k], p2[k], xx);
    }

    // store into split layout [half][c][b][d][HS]
    size_t row = ((size_t)(c * NB + b) * DM + d) * HS;
#pragma unroll
    for (int h = 0; h < 2; h++) {
        float4* pe = (float4*)(g_end + (size_t)h * (NC - 1) * SLAB + row);
#pragma unroll
        for (int k = 0; k < 2; k++) {
            float a0, a1, a2, a3;
            upk(p2[4 * h + 2 * k], a0, a1);
            upk(p2[4 * h + 2 * k + 1], a2, a3);
            pe[k] = make_float4(a0, a1, a2, a3);
        }
    }
}

// ---- phase C: split state, inline params + init reconstruction + output ----
__global__ void __launch_bounds__(BDIM)
k_C(const float* __restrict__ x,
    const float* __restrict__ A_log,
    const float* __restrict__ Bm,
    const float* __restrict__ Cm,
    const float* __restrict__ log_dt,
    float* __restrict__ y) {
    int tid  = blockIdx.x * BDIM + threadIdx.x;  // 2*NC*NB*DM = 262144
    int lane = threadIdx.x & 31;
    int half = lane >> 4;
    int pidx = ((tid >> 5) << 4) | (lane & 15);  // (c,b,d), c in 0..NC-1
    int d = pidx & (DM - 1);
    int b = (pidx >> 11) & (NB - 1);
    int c = pidx >> 14;

    float dt = __expf(log_dt[d]);                // DT_SCALE = 1
    ull dA2[4];
    {
        const float4* pa = (const float4*)(A_log + (d << 4) + half * HS);
#pragma unroll
        for (int k = 0; k < 2; k++) {
            float4 v = pa[k];
            float a0 = __expf(dt * __expf(v.x));
            float a1 = __expf(dt * __expf(v.y));
            float a2 = __expf(dt * __expf(v.z));
            float a3 = __expf(dt * __expf(v.w));
            dA2[2 * k]     = pk(a0, a1);
            dA2[2 * k + 1] = pk(a2, a3);
        }
    }

    ull cb2[4];
    {
        const float4* pb = (const float4*)(Bm + (d << 4) + half * HS);
        const float4* pc = (const float4*)(Cm + (d << 4) + half * HS);
#pragma unroll
        for (int k = 0; k < 2; k++) {
            float4 vb = pb[k];
            float4 vc = pc[k];
            cb2[2 * k]     = pk(vc.x * (dt * vb.x), vc.y * (dt * vb.y));
            cb2[2 * k + 1] = pk(vc.z * (dt * vb.z), vc.w * (dt * vb.w));
        }
    }

    ull p2[4];
#pragma unroll
    for (int k = 0; k < 4; k++) p2[k] = 0ull;

    // init = scan of prior chunk end-states with dA^LC (c uniform per block)
    if (c > 0) {
        ull dAL2[4];
        {
            const float4* pa = (const float4*)(A_log + (d << 4) + half * HS);
#pragma unroll
            for (int k = 0; k < 2; k++) {
                float4 v = pa[k];
                float a0 = __expf((float)LC * dt * __expf(v.x));
                float a1 = __expf((float)LC * dt * __expf(v.y));
                float a2 = __expf((float)LC * dt * __expf(v.z));
                float a3 = __expf((float)LC * dt * __expf(v.w));
                dAL2[2 * k]     = pk(a0, a1);
                dAL2[2 * k + 1] = pk(a2, a3);
            }
        }
        size_t hb = (size_t)half * (NC - 1) * SLAB + (size_t)b * DM * HS
                  + (size_t)d * HS;
        for (int cc = 0; cc < c; cc++) {
            const float4* pe = (const float4*)(g_end + hb + (size_t)cc * SLAB);
#pragma unroll
            for (int k = 0; k < 2; k++) {
                float4 v = pe[k];
                p2[2 * k]     = fma2(dAL2[2 * k],     p2[2 * k],     pk(v.x, v.y));
                p2[2 * k + 1] = fma2(dAL2[2 * k + 1], p2[2 * k + 1], pk(v.z, v.w));
            }
        }
    }

    size_t off = (size_t)(b * LQ + c * LC) * DM + d;
    const float* xp = x + off;
    float*       yp = y + off;

#pragma unroll 8
    for (int t = 0; t < LC; t++) {
        float xt = xp[(size_t)t * DM];
        ull xx = pk(xt, xt);
#pragma unroll
        for (int k = 0; k < 4; k++) p2[k] = fma2(dA2[k], p2[k], xx);

        ull acc0 = mul2(cb2[0], p2[0]);
        ull acc1 = mul2(cb2[1], p2[1]);
        acc0 = fma2(cb2[2], p2[2], acc0);
        acc1 = fma2(cb2[3], p2[3], acc1);
        ull acc = add2(acc0, acc1);
        float s0, s1;
        upk(acc, s0, s1);
        float s = s0 + s1;
        s += __shfl_xor_sync(0xffffffffu, s, 16);
        if (half == 0) yp[(size_t)t * DM] = s;
    }
}

extern "C" void kernel_launch(void* const* d_in, const int* in_sizes, int n_in,
                              void* d_out, int out_size) {
    const float* x      = (const float*)d_in[0];
    const float* A_log  = (const float*)d_in[1];
    const float* B      = (const float*)d_in[2];
    const float* C      = (const float*)d_in[3];
    const float* log_dt = (const float*)d_in[4];
    float* y = (float*)d_out;

    k_A<<<((NC - 1) * NB * DM) / BDIM, BDIM>>>(x, A_log, log_dt);
    k_C<<<(2 * NC * NB * DM) / BDIM, BDIM>>>(x, A_log, B, C, log_dt, y);
}

// round 16
// speedup vs baseline: 1.0215x; 1.0215x over previous
#include <cuda_runtime.h>

#define DM   2048   // d_model
#define DS   16     // d_state
#define NB   8      // batch
#define LQ   512    // seq
#define NC   8      // chunks
#define LC   64     // chunk length (NC*LC == LQ)
#define HS   8      // states per thread in C role (half of DS)

#define BDIM 128
#define SLAB (NB * DM * HS)                  // 131072 floats per (half,chunk)
#define NBLK_A ((NC - 1) * NB * DM / BDIM)   // 896 A-role blocks
#define NBLK_C0 (2 * NB * DM / BDIM)         // 256 chunk-0 C-role blocks

typedef unsigned long long ull;

// ---- chunk end-state scratch, split layout [half][c][b][d][HS] ----
__device__ float g_end[2 * (NC - 1) * SLAB];

// ---- packed f32x2 helpers ----
__device__ __forceinline__ ull pk(float lo, float hi) {
    ull r;
    asm("mov.b64 %0, {%1, %2};" : "=l"(r) : "f"(lo), "f"(hi));
    return r;
}
__device__ __forceinline__ void upk(ull v, float& lo, float& hi) {
    asm("mov.b64 {%0, %1}, %2;" : "=f"(lo), "=f"(hi) : "l"(v));
}
__device__ __forceinline__ ull fma2(ull a, ull b, ull c) {
    ull r;
    asm("fma.rn.f32x2 %0, %1, %2, %3;" : "=l"(r) : "l"(a), "l"(b), "l"(c));
    return r;
}
__device__ __forceinline__ ull mul2(ull a, ull b) {
    ull r;
    asm("mul.rn.f32x2 %0, %1, %2;" : "=l"(r) : "l"(a), "l"(b));
    return r;
}
__device__ __forceinline__ ull add2(ull a, ull b) {
    ull r;
    asm("add.rn.f32x2 %0, %1, %2;" : "=l"(r) : "l"(a), "l"(b));
    return r;
}

// ---- split-state C-role body for one (c,b,d,half) thread ----
__device__ __forceinline__ void c_role(int tid, int lane, int c_base,
                                       const float* __restrict__ x,
                                       const float* __restrict__ A_log,
                                       const float* __restrict__ Bm,
                                       const float* __restrict__ Cm,
                                       const float* __restrict__ log_dt,
                                       float* __restrict__ y) {
    int half = lane >> 4;
    int pidx = ((tid >> 5) << 4) | (lane & 15);
    int d = pidx & (DM - 1);
    int b = (pidx >> 11) & (NB - 1);
    int c = c_base + (pidx >> 14);

    float dt = __expf(log_dt[d]);                // DT_SCALE = 1
    ull dA2[4];
    {
        const float4* pa = (const float4*)(A_log + (d << 4) + half * HS);
#pragma unroll
        for (int k = 0; k < 2; k++) {
            float4 v = pa[k];
            float a0 = __expf(dt * __expf(v.x));
            float a1 = __expf(dt * __expf(v.y));
            float a2 = __expf(dt * __expf(v.z));
            float a3 = __expf(dt * __expf(v.w));
            dA2[2 * k]     = pk(a0, a1);
            dA2[2 * k + 1] = pk(a2, a3);
        }
    }

    ull cb2[4];
    {
        const float4* pb = (const float4*)(Bm + (d << 4) + half * HS);
        const float4* pc = (const float4*)(Cm + (d << 4) + half * HS);
#pragma unroll
        for (int k = 0; k < 2; k++) {
            float4 vb = pb[k];
            float4 vc = pc[k];
            cb2[2 * k]     = pk(vc.x * (dt * vb.x), vc.y * (dt * vb.y));
            cb2[2 * k + 1] = pk(vc.z * (dt * vb.z), vc.w * (dt * vb.w));
        }
    }

    ull p2[4];
#pragma unroll
    for (int k = 0; k < 4; k++) p2[k] = 0ull;

    // init = scan of prior chunk end-states with dA^LC
    if (c > 0) {
        ull dAL2[4];
        {
            const float4* pa = (const float4*)(A_log + (d << 4) + half * HS);
#pragma unroll
            for (int k = 0; k < 2; k++) {
                float4 v = pa[k];
                float a0 = __expf((float)LC * dt * __expf(v.x));
                float a1 = __expf((float)LC * dt * __expf(v.y));
                float a2 = __expf((float)LC * dt * __expf(v.z));
                float a3 = __expf((float)LC * dt * __expf(v.w));
                dAL2[2 * k]     = pk(a0, a1);
                dAL2[2 * k + 1] = pk(a2, a3);
            }
        }
        size_t hb = (size_t)half * (NC - 1) * SLAB + (size_t)b * DM * HS
                  + (size_t)d * HS;
        for (int cc = 0; cc < c; cc++) {
            const float4* pe = (const float4*)(g_end + hb + (size_t)cc * SLAB);
#pragma unroll
            for (int k = 0; k < 2; k++) {
                float4 v = pe[k];
                p2[2 * k]     = fma2(dAL2[2 * k],     p2[2 * k],     pk(v.x, v.y));
                p2[2 * k + 1] = fma2(dAL2[2 * k + 1], p2[2 * k + 1], pk(v.z, v.w));
            }
        }
    }

    size_t off = (size_t)(b * LQ + c * LC) * DM + d;
    const float* xp = x + off;
    float*       yp = y + off;

#pragma unroll 8
    for (int t = 0; t < LC; t++) {
        float xt = xp[(size_t)t * DM];
        ull xx = pk(xt, xt);
#pragma unroll
        for (int k = 0; k < 4; k++) p2[k] = fma2(dA2[k], p2[k], xx);

        ull acc0 = mul2(cb2[0], p2[0]);
        ull acc1 = mul2(cb2[1], p2[1]);
        acc0 = fma2(cb2[2], p2[2], acc0);
        acc1 = fma2(cb2[3], p2[3], acc1);
        ull acc = add2(acc0, acc1);
        float s0, s1;
        upk(acc, s0, s1);
        float s = s0 + s1;
        s += __shfl_xor_sync(0xffffffffu, s, 16);
        if (half == 0) yp[(size_t)t * DM] = s;
    }
}

// ---- kernel1: A-role blocks (end states, chunks 0..6) + chunk-0 C blocks ----
// The two roles are fully independent — no flags, no waiting.
__global__ void __launch_bounds__(BDIM)
k_AC0(const float* __restrict__ x,
      const float* __restrict__ A_log,
      const float* __restrict__ Bm,
      const float* __restrict__ Cm,
      const float* __restrict__ log_dt,
      float* __restrict__ y) {
    if (blockIdx.x < NBLK_A) {
        // ---- A role: full-state end-state scan of chunk c ----
        int idx = blockIdx.x * BDIM + threadIdx.x;   // (c,b,d)
        int d = idx & (DM - 1);
        int b = (idx >> 11) & (NB - 1);
        int c = idx >> 14;                           // 0..NC-2

        float dt = __expf(log_dt[d]);
        ull dA2[8];
        {
            const float4* pa = (const float4*)(A_log + (d << 4));
#pragma unroll
            for (int k = 0; k < 4; k++) {
                float4 v = pa[k];
                float a0 = __expf(dt * __expf(v.x));
                float a1 = __expf(dt * __expf(v.y));
                float a2 = __expf(dt * __expf(v.z));
                float a3 = __expf(dt * __expf(v.w));
                dA2[2 * k]     = pk(a0, a1);
                dA2[2 * k + 1] = pk(a2, a3);
            }
        }

        ull p2[8];
#pragma unroll
        for (int k = 0; k < 8; k++) p2[k] = 0ull;

        const float* xp = x + (size_t)(b * LQ + c * LC) * DM + d;
#pragma unroll 8
        for (int t = 0; t < LC; t++) {
            float xt = xp[(size_t)t * DM];
            ull xx = pk(xt, xt);
#pragma unroll
            for (int k = 0; k < 8; k++) p2[k] = fma2(dA2[k], p2[k], xx);
        }

        size_t row = ((size_t)(c * NB + b) * DM + d) * HS;
#pragma unroll
        for (int h = 0; h < 2; h++) {
            float4* pe = (float4*)(g_end + (size_t)h * (NC - 1) * SLAB + row);
#pragma unroll
            for (int k = 0; k < 2; k++) {
                float a0, a1, a2, a3;
                upk(p2[4 * h + 2 * k], a0, a1);
                upk(p2[4 * h + 2 * k + 1], a2, a3);
                pe[k] = make_float4(a0, a1, a2, a3);
            }
        }
    } else {
        // ---- C role for chunk 0 (no dependency on A blocks) ----
        int tid = (blockIdx.x - NBLK_A) * BDIM + threadIdx.x;
        c_role(tid, threadIdx.x & 31, 0, x, A_log, Bm, Cm, log_dt, y);
    }
}

// ---- kernel2: C role for chunks 1..7 ----
__global__ void __launch_bounds__(BDIM)
k_C(const float* __restrict__ x,
    const float* __restrict__ A_log,
    const float* __restrict__ Bm,
    const float* __restrict__ Cm,
    const float* __restrict__ log_dt,
    float* __restrict__ y) {
    int tid = blockIdx.x * BDIM + threadIdx.x;   // 2*(NC-1)*NB*DM threads
    c_role(tid, threadIdx.x & 31, 1, x, A_log, Bm, Cm, log_dt, y);
}

extern "C" void kernel_launch(void* const* d_in, const int* in_sizes, int n_in,
                              void* d_out, int out_size) {
    const float* x      = (const float*)d_in[0];
    const float* A_log  = (const float*)d_in[1];
    const float* B      = (const float*)d_in[2];
    const float* C      = (const float*)d_in[3];
    const float* log_dt = (const float*)d_in[4];
    float* y = (float*)d_out;

    k_AC0<<<NBLK_A + NBLK_C0, BDIM>>>(x, A_log, B, C, log_dt, y);
    k_C<<<(2 * (NC - 1) * NB * DM) / BDIM, BDIM>>>(x, A_log, B, C, log_dt, y);
}